// round 13
// baseline (speedup 1.0000x reference)
#include <cuda_runtime.h>
#include <cstdint>

#define BB 128
#define NN 512
#define FF 5
#define HH 64
#define KK 16

typedef unsigned long long u64;

// Scratch (device globals: allocation-free)
__device__ __align__(256) float g_hA[BB * NN * HH];        // 16 MB
__device__ __align__(256) float g_hB[BB * NN * HH];        // 16 MB
__device__ __align__(256) float g_av[BB * NN * 2 * HH];    // 32 MB: per node [c | v]
__device__ __align__(256) int   g_idx[BB * NN * KK];       // 4 MB

__device__ __forceinline__ float elu_f(float x) {
    return x > 0.f ? x : (__expf(x) - 1.f);
}

// ---- packed fp32x2 helpers (Blackwell FFMA2; exact fp32) ---------------
__device__ __forceinline__ u64 fma2_(u64 a, u64 b, u64 c) {
    u64 d;
    asm("fma.rn.f32x2 %0, %1, %2, %3;" : "=l"(d) : "l"(a), "l"(b), "l"(c));
    return d;
}
__device__ __forceinline__ u64 pack2_(float x) {
    u64 d;
    asm("mov.b64 %0, {%1, %1};" : "=l"(d) : "f"(x));
    return d;
}
__device__ __forceinline__ float2 unpack2_(u64 v) {
    float2 r;
    asm("mov.b64 {%0, %1}, %2;" : "=f"(r.x), "=f"(r.y) : "l"(v));
    return r;
}
__device__ __forceinline__ uint32_t smem_u32(const void* p) {
    uint32_t a;
    asm("{ .reg .u64 t; cvta.to.shared.u64 t, %1; cvt.u32.u64 %0, t; }" : "=r"(a) : "l"(p));
    return a;
}
__device__ __forceinline__ void cpasync16(uint32_t saddr, const void* g) {
    asm volatile("cp.async.cg.shared.global [%0], [%1], 16;" :: "r"(saddr), "l"(g));
}
#define CP_COMMIT() asm volatile("cp.async.commit_group;" ::: "memory")
#define CP_WAIT1()  asm volatile("cp.async.wait_group 1;" ::: "memory")

// ---------------------------------------------------------------------------
// Input MLP: x[B,N,5] -> h[B,N,64], three elu layers.
// ---------------------------------------------------------------------------
__global__ __launch_bounds__(256) void input_kernel(
    const float* __restrict__ x,
    const float* __restrict__ W0, const float* __restrict__ b0,
    const float* __restrict__ W1, const float* __restrict__ b1,
    const float* __restrict__ W2, const float* __restrict__ b2,
    float* __restrict__ out)
{
    __shared__ float sW0[FF * HH];
    __shared__ float sW1[HH * HH];
    __shared__ float sW2[HH * HH];
    __shared__ float sx[16][FF];
    __shared__ float sh[16][HH];

    int tid = threadIdx.x;
    for (int t = tid; t < FF * HH; t += 256) sW0[t] = W0[t];
    for (int t = tid; t < HH * HH; t += 256) { sW1[t] = W1[t]; sW2[t] = W2[t]; }

    int node0 = blockIdx.x * 16;
    if (tid < 16 * FF) sx[tid / FF][tid % FF] = x[(size_t)(node0 + tid / FF) * FF + tid % FF];
    __syncthreads();

    int nl = tid >> 4, tn = tid & 15;

    float4 acc = *(const float4*)(b0 + tn * 4);
    #pragma unroll
    for (int d = 0; d < FF; d++) {
        float v = sx[nl][d];
        float4 w = *(const float4*)(sW0 + d * HH + tn * 4);
        acc.x = fmaf(v, w.x, acc.x); acc.y = fmaf(v, w.y, acc.y);
        acc.z = fmaf(v, w.z, acc.z); acc.w = fmaf(v, w.w, acc.w);
    }
    acc.x = elu_f(acc.x); acc.y = elu_f(acc.y); acc.z = elu_f(acc.z); acc.w = elu_f(acc.w);
    ((float4*)(sh[nl]))[tn] = acc;
    __syncthreads();

    float4 a2 = *(const float4*)(b1 + tn * 4);
    #pragma unroll 8
    for (int d = 0; d < HH; d++) {
        float v = sh[nl][d];
        float4 w = *(const float4*)(sW1 + d * HH + tn * 4);
        a2.x = fmaf(v, w.x, a2.x); a2.y = fmaf(v, w.y, a2.y);
        a2.z = fmaf(v, w.z, a2.z); a2.w = fmaf(v, w.w, a2.w);
    }
    __syncthreads();
    a2.x = elu_f(a2.x); a2.y = elu_f(a2.y); a2.z = elu_f(a2.z); a2.w = elu_f(a2.w);
    ((float4*)(sh[nl]))[tn] = a2;
    __syncthreads();

    float4 a3 = *(const float4*)(b2 + tn * 4);
    #pragma unroll 8
    for (int d = 0; d < HH; d++) {
        float v = sh[nl][d];
        float4 w = *(const float4*)(sW2 + d * HH + tn * 4);
        a3.x = fmaf(v, w.x, a3.x); a3.y = fmaf(v, w.y, a3.y);
        a3.z = fmaf(v, w.z, a3.z); a3.w = fmaf(v, w.w, a3.w);
    }
    a3.x = elu_f(a3.x); a3.y = elu_f(a3.y); a3.z = elu_f(a3.z); a3.w = elu_f(a3.w);
    *(float4*)(out + (size_t)(node0 + nl) * HH + tn * 4) = a3;
}

// ---------------------------------------------------------------------------
// kNN with warm-up + candidate-queue top-k (exact fp32 selection). FROZEN.
// ---------------------------------------------------------------------------
#define STK_CAP 8
#define STK_STRIDE 9
#define KNN_SMEM ((NN * HH + NN) * 4 + NN * STK_STRIDE * 8)

#define TOPK_INSERT(DJ, J)                                                   \
    if ((DJ) < worst) {                                                      \
        _Pragma("unroll")                                                    \
        for (int t = 0; t < KK; t++) if (t == wslot) { bd[t] = (DJ); bi[t] = (J); } \
        float w_ = bd[0]; int ws_ = 0;                                       \
        _Pragma("unroll")                                                    \
        for (int t = 1; t < KK; t++) if (bd[t] > w_) { w_ = bd[t]; ws_ = t; } \
        worst = w_; wslot = ws_;                                             \
    }

__global__ __launch_bounds__(512, 1) void knn_kernel(
    const float* __restrict__ h, int* __restrict__ nbr)
{
    extern __shared__ float sm[];
    float* sq = sm + NN * HH;
    u64* stkbase = (u64*)(sm + NN * HH + NN);
    int b = blockIdx.x, i = threadIdx.x;
    u64* stk = stkbase + i * STK_STRIDE;

    const float4* src4 = (const float4*)(h + (size_t)b * NN * HH);
    float4* dst4 = (float4*)sm;
    for (int t = i; t < NN * HH / 4; t += NN) dst4[t] = src4[t];
    __syncthreads();

    u64 rp[HH / 2];
    const ulonglong2* myrow = (const ulonglong2*)(sm + i * HH);
    #pragma unroll
    for (int q = 0; q < HH / 4; q++) {
        ulonglong2 v = myrow[q];
        rp[2 * q] = v.x; rp[2 * q + 1] = v.y;
    }
    u64 s2 = 0ull;
    #pragma unroll
    for (int q = 0; q < HH / 2; q++) s2 = fma2_(rp[q], rp[q], s2);
    float2 sf = unpack2_(s2);
    float s = sf.x + sf.y;
    sq[i] = s;
    __syncthreads();

    float bd[KK]; int bi[KK];
    #pragma unroll
    for (int t = 0; t < KK; t++) { bd[t] = 1e30f; bi[t] = 0; }
    float worst = 1e30f; int wslot = 0;

    for (int j = 0; j < 32; j += 2) {
        const ulonglong2* r0 = (const ulonglong2*)(sm + j * HH);
        const ulonglong2* r1 = (const ulonglong2*)(sm + j * HH + HH);
        u64 a0 = 0ull, a1 = 0ull;
        #pragma unroll
        for (int q = 0; q < HH / 4; q++) {
            ulonglong2 v0 = r0[q];
            a0 = fma2_(rp[2 * q], v0.x, a0);
            a0 = fma2_(rp[2 * q + 1], v0.y, a0);
            ulonglong2 v1 = r1[q];
            a1 = fma2_(rp[2 * q], v1.x, a1);
            a1 = fma2_(rp[2 * q + 1], v1.y, a1);
        }
        float2 f0 = unpack2_(a0), f1 = unpack2_(a1);
        float dj0 = s + sq[j]     - 2.f * (f0.x + f0.y);
        float dj1 = s + sq[j + 1] - 2.f * (f1.x + f1.y);
        if (j == i)     dj0 = 1e30f;
        if (j + 1 == i) dj1 = 1e30f;
        TOPK_INSERT(dj0, j)
        TOPK_INSERT(dj1, j + 1)
    }

    int cnt = 0;
    for (int j = 32; j < NN; j += 2) {
        const ulonglong2* r0 = (const ulonglong2*)(sm + j * HH);
        const ulonglong2* r1 = (const ulonglong2*)(sm + j * HH + HH);
        u64 a0 = 0ull, a1 = 0ull;
        #pragma unroll
        for (int q = 0; q < HH / 4; q++) {
            ulonglong2 v0 = r0[q];
            a0 = fma2_(rp[2 * q], v0.x, a0);
            a0 = fma2_(rp[2 * q + 1], v0.y, a0);
            ulonglong2 v1 = r1[q];
            a1 = fma2_(rp[2 * q], v1.x, a1);
            a1 = fma2_(rp[2 * q + 1], v1.y, a1);
        }
        float2 f0 = unpack2_(a0), f1 = unpack2_(a1);
        float dj0 = s + sq[j]     - 2.f * (f0.x + f0.y);
        float dj1 = s + sq[j + 1] - 2.f * (f1.x + f1.y);
        if (j == i)     dj0 = 1e30f;
        if (j + 1 == i) dj1 = 1e30f;

        if (dj0 < worst) { stk[cnt] = ((u64)__float_as_uint(dj0) << 32) | (unsigned)j; cnt++; }
        if (dj1 < worst) { stk[cnt] = ((u64)__float_as_uint(dj1) << 32) | (unsigned)(j + 1); cnt++; }
        if (__any_sync(0xffffffffu, cnt >= STK_CAP - 1)) {
            #pragma unroll
            for (int t = 0; t < STK_CAP; t++) {
                if (t < cnt) {
                    u64 e = stk[t];
                    float dd = __uint_as_float((unsigned)(e >> 32));
                    int jj = (int)(e & 0xffffffffull);
                    TOPK_INSERT(dd, jj)
                }
            }
            cnt = 0;
        }
    }
    #pragma unroll
    for (int t = 0; t < STK_CAP; t++) {
        if (t < cnt) {
            u64 e = stk[t];
            float dd = __uint_as_float((unsigned)(e >> 32));
            int jj = (int)(e & 0xffffffffull);
            TOPK_INSERT(dd, jj)
        }
    }

    #pragma unroll
    for (int t = 0; t < KK; t++) nbr[((size_t)b * NN + i) * KK + t] = bi[t];
}

// ---------------------------------------------------------------------------
// Per-node precompute: c = h@W0top + b0 - h@W0bot, v = h@W0bot.
// (E row = elu(c_i + v_j).)  av[n] = [c(64) | v(64)].
// ---------------------------------------------------------------------------
#define AV_GROUPS (BB * NN / 16)   // 4096

__global__ __launch_bounds__(256, 1) void av_kernel(
    const float* __restrict__ h,
    const float* __restrict__ W0, const float* __restrict__ b0,
    float* __restrict__ av)
{
    __shared__ float sW[2 * HH * HH];    // 32 KB (top | bottom)
    __shared__ float sh[16][HH];
    __shared__ float sb[HH];

    int tid = threadIdx.x;
    for (int t = tid; t < 2 * HH * HH; t += 256) sW[t] = W0[t];
    if (tid < HH) sb[tid] = b0[tid];
    __syncthreads();

    int nl = tid >> 4, tn = tid & 15;

    for (int grp = blockIdx.x; grp < AV_GROUPS; grp += gridDim.x) {
        int node0 = grp * 16;
        {
            int row = tid >> 4, q = tid & 15;
            ((float4*)sh[row])[q] = *(const float4*)(h + (size_t)(node0 + row) * HH + q * 4);
        }
        __syncthreads();

        float4 aA = *(const float4*)(sb + tn * 4);
        float4 aV = make_float4(0.f, 0.f, 0.f, 0.f);
        #pragma unroll 8
        for (int d = 0; d < HH; d++) {
            float v = sh[nl][d];
            float4 wt = *(const float4*)(sW + d * HH + tn * 4);
            float4 wb = *(const float4*)(sW + (HH + d) * HH + tn * 4);
            aA.x = fmaf(v, wt.x, aA.x); aA.y = fmaf(v, wt.y, aA.y);
            aA.z = fmaf(v, wt.z, aA.z); aA.w = fmaf(v, wt.w, aA.w);
            aV.x = fmaf(v, wb.x, aV.x); aV.y = fmaf(v, wb.y, aV.y);
            aV.z = fmaf(v, wb.z, aV.z); aV.w = fmaf(v, wb.w, aV.w);
        }
        float4 cC = make_float4(aA.x - aV.x, aA.y - aV.y, aA.z - aV.z, aA.w - aV.w);
        *(float4*)(av + (size_t)(node0 + nl) * 128 + tn * 4) = cC;
        *(float4*)(av + (size_t)(node0 + nl) * 128 + 64 + tn * 4) = aV;
        __syncthreads();
    }
}

// ---------------------------------------------------------------------------
// EdgeConv, warp-autonomous + cp.async double-buffer, 3 CTAs/SM:
//   192 threads (6 warps), __launch_bounds__(192,3) -> 18 warps/SM.
//   GEMM lane tile retiled to 4 rows x 8 cols (acc 16 u64, ev 4 float4):
//   fewer regs + fewer crossbar phases (w2 loads 8-lane distinct, 4-row bcast).
// smem/CTA: W1 4096 + b1 64 + 6 warps * 2304 = 17984 floats (~71.9 KB)
// ---------------------------------------------------------------------------
#define ED_B1f  4096
#define ED_BUFf 4160
#define ED_WBUF 2304                 // floats per warp (2 bufs x 1152)
#define ED_NW   6
#define EDGE_FLOATS (ED_BUFf + ED_NW * ED_WBUF)
#define EDGE_SMEM (EDGE_FLOATS * 4)
#define ED_TOT (BB * NN)

__global__ __launch_bounds__(192, 3) void edge_kernel(
    const float* __restrict__ av, const int* __restrict__ nbr,
    const float* __restrict__ W1, const float* __restrict__ b1,
    float* __restrict__ out)
{
    extern __shared__ float sm[];
    float* sW1 = sm;
    float* sB1 = sm + ED_B1f;

    int tid = threadIdx.x, wid = tid >> 5, lid = tid & 31;
    float* wbase = sm + ED_BUFf + wid * ED_WBUF;
    uint32_t wbase_u = smem_u32(wbase);

    {   // weights + bias once
        const float4* w14 = (const float4*)W1; float4* s14 = (float4*)sW1;
        for (int t = tid; t < 1024; t += 192) s14[t] = w14[t];
        if (tid < 64) sB1[tid] = b1[tid];
    }
    __syncthreads();

    int mrow = lid >> 1, half = lid & 1;          // gather/build: row, col-half
    int c0 = half * 32;
    int tmp = lid >> 3, tc = lid & 7;             // GEMM: 4-row group, 8-col group
    int m0 = tmp * 4;
    int cb = tc * 8;

    int nwarps = gridDim.x * ED_NW;
    int ni0 = blockIdx.x * ED_NW + wid;

    // ---- prologue: cp.async item ni0 into buf 0
    {
        int j0 = nbr[(size_t)ni0 * KK + mrow];
        uint32_t dstV = wbase_u + (uint32_t)((mrow * 68 + c0) * 4);
        const float* srcV = av + ((size_t)(ni0 & ~(NN - 1)) + j0) * 128 + 64 + c0;
        #pragma unroll
        for (int q = 0; q < 8; q++) cpasync16(dstV + q * 16, srcV + q * 4);
        if (lid < 16)
            cpasync16(wbase_u + (uint32_t)((1088 + lid * 4) * 4),
                      av + (size_t)ni0 * 128 + lid * 4);
    }
    CP_COMMIT();
    int jn1 = (ni0 + nwarps < ED_TOT) ? nbr[(size_t)(ni0 + nwarps) * KK + mrow] : 0;

    int bsel = 0;
    for (int ni = ni0; ni < ED_TOT; ni += nwarps) {
        int ni1 = ni + nwarps;
        int ni2 = ni + 2 * nwarps;
        int jn2 = (ni2 < ED_TOT) ? nbr[(size_t)ni2 * KK + mrow] : 0;

        // ---- cp.async item i+1 into the other buffer
        if (ni1 < ED_TOT) {
            uint32_t bb = (uint32_t)((bsel ^ 1) * 1152);
            uint32_t dstV = wbase_u + (bb + (uint32_t)(mrow * 68 + c0)) * 4;
            const float* srcV = av + ((size_t)(ni1 & ~(NN - 1)) + jn1) * 128 + 64 + c0;
            #pragma unroll
            for (int q = 0; q < 8; q++) cpasync16(dstV + q * 16, srcV + q * 4);
            if (lid < 16)
                cpasync16(wbase_u + (bb + 1088u + (uint32_t)(lid * 4)) * 4,
                          av + (size_t)ni1 * 128 + lid * 4);
        }
        CP_COMMIT();

        // ---- current buffer is complete (committed one iteration ago)
        CP_WAIT1();
        __syncwarp();

        float* rawV = wbase + bsel * 1152;
        float* rawC = rawV + 1088;

        // ---- E-build: in-place elu(c_i + v_j) on own slots
        {
            float4* e4 = (float4*)(rawV + mrow * 68 + c0);
            const float4* cc = (const float4*)(rawC + c0);
            #pragma unroll
            for (int q = 0; q < 8; q++) {
                float4 c = cc[q], v = e4[q];
                float4 e;
                e.x = elu_f(c.x + v.x);
                e.y = elu_f(c.y + v.y);
                e.z = elu_f(c.z + v.z);
                e.w = elu_f(c.w + v.w);
                e4[q] = e;
            }
        }
        __syncwarp();

        // ---- GEMM2: E(16x64) @ W1(64x64); lane: rows m0..m0+3, cols cb..cb+8
        u64 acc[4][4];
        #pragma unroll
        for (int r = 0; r < 4; r++)
            { acc[r][0] = 0ull; acc[r][1] = 0ull; acc[r][2] = 0ull; acc[r][3] = 0ull; }
        #pragma unroll 2
        for (int d0 = 0; d0 < HH; d0 += 4) {
            float4 ev[4];
            #pragma unroll
            for (int r = 0; r < 4; r++)
                ev[r] = *(const float4*)(rawV + (m0 + r) * 68 + d0);
            #pragma unroll
            for (int dd = 0; dd < 4; dd++) {
                ulonglong2 wA = *(const ulonglong2*)(sW1 + (d0 + dd) * HH + cb);
                ulonglong2 wB = *(const ulonglong2*)(sW1 + (d0 + dd) * HH + cb + 4);
                #pragma unroll
                for (int r = 0; r < 4; r++) {
                    float a = (dd == 0) ? ev[r].x : (dd == 1) ? ev[r].y
                            : (dd == 2) ? ev[r].z : ev[r].w;
                    u64 a2 = pack2_(a);
                    acc[r][0] = fma2_(a2, wA.x, acc[r][0]);
                    acc[r][1] = fma2_(a2, wA.y, acc[r][1]);
                    acc[r][2] = fma2_(a2, wB.x, acc[r][2]);
                    acc[r][3] = fma2_(a2, wB.y, acc[r][3]);
                }
            }
        }

        // ---- epilogue: bias + elu + 4-row sum; combine 4 row-groups via shfl
        float4 bbA = *(const float4*)(sB1 + cb);
        float4 bbB = *(const float4*)(sB1 + cb + 4);
        float s[8];
        #pragma unroll
        for (int i2 = 0; i2 < 8; i2++) s[i2] = 0.f;
        #pragma unroll
        for (int r = 0; r < 4; r++) {
            float2 p0 = unpack2_(acc[r][0]);
            float2 p1 = unpack2_(acc[r][1]);
            float2 p2 = unpack2_(acc[r][2]);
            float2 p3 = unpack2_(acc[r][3]);
            s[0] += elu_f(p0.x + bbA.x);
            s[1] += elu_f(p0.y + bbA.y);
            s[2] += elu_f(p1.x + bbA.z);
            s[3] += elu_f(p1.y + bbA.w);
            s[4] += elu_f(p2.x + bbB.x);
            s[5] += elu_f(p2.y + bbB.y);
            s[6] += elu_f(p3.x + bbB.z);
            s[7] += elu_f(p3.y + bbB.w);
        }
        // shfl tree doubles as the warp barrier before next in-place build
        #pragma unroll
        for (int i2 = 0; i2 < 8; i2++) s[i2] += __shfl_down_sync(0xffffffffu, s[i2], 8);
        #pragma unroll
        for (int i2 = 0; i2 < 8; i2++) s[i2] += __shfl_down_sync(0xffffffffu, s[i2], 16);
        if (lid < 8) {
            float* op = out + (size_t)ni * HH + cb;
            *(float4*)(op)     = make_float4(s[0], s[1], s[2], s[3]);
            *(float4*)(op + 4) = make_float4(s[4], s[5], s[6], s[7]);
        }

        jn1 = jn2;
        bsel ^= 1;
    }
}

// ---------------------------------------------------------------------------
// Global max-pool + output MLP + log_softmax. One CTA (64 threads) per graph.
// ---------------------------------------------------------------------------
__global__ __launch_bounds__(64) void pool_kernel(
    const float* __restrict__ h,
    const float* __restrict__ W0, const float* __restrict__ b0,
    const float* __restrict__ W1, const float* __restrict__ b1,
    const float* __restrict__ W2, const float* __restrict__ b2,
    float* __restrict__ out)
{
    __shared__ float sW0[HH * HH], sW1[HH * HH], sW2[HH * 10];
    __shared__ float g0[HH], g1[HH], lg[10];

    int b = blockIdx.x, f = threadIdx.x;
    for (int t = f; t < HH * HH; t += 64) { sW0[t] = W0[t]; sW1[t] = W1[t]; }
    for (int t = f; t < HH * 10; t += 64) sW2[t] = W2[t];

    const float* hb = h + (size_t)b * NN * HH;
    float m0 = -1e30f, m1 = -1e30f, m2 = -1e30f, m3 = -1e30f;
    #pragma unroll 4
    for (int n = 0; n < NN; n += 4) {
        m0 = fmaxf(m0, hb[(n + 0) * HH + f]);
        m1 = fmaxf(m1, hb[(n + 1) * HH + f]);
        m2 = fmaxf(m2, hb[(n + 2) * HH + f]);
        m3 = fmaxf(m3, hb[(n + 3) * HH + f]);
    }
    g0[f] = fmaxf(fmaxf(m0, m1), fmaxf(m2, m3));
    __syncthreads();

    float acc = b0[f];
    #pragma unroll 8
    for (int d = 0; d < HH; d++) acc = fmaf(g0[d], sW0[d * HH + f], acc);
    g1[f] = elu_f(acc);
    __syncthreads();

    acc = b1[f];
    #pragma unroll 8
    for (int d = 0; d < HH; d++) acc = fmaf(g1[d], sW1[d * HH + f], acc);
    __syncthreads();
    g0[f] = elu_f(acc);
    __syncthreads();

    if (f < 10) {
        float a = b2[f];
        #pragma unroll 8
        for (int d = 0; d < HH; d++) a = fmaf(g0[d], sW2[d * 10 + f], a);
        lg[f] = a;
    }
    __syncthreads();

    if (f == 0) {
        float mx = lg[0];
        #pragma unroll
        for (int c = 1; c < 10; c++) mx = fmaxf(mx, lg[c]);
        float se = 0.f;
        #pragma unroll
        for (int c = 0; c < 10; c++) se += expf(lg[c] - mx);
        float lse = mx + logf(se);
        #pragma unroll
        for (int c = 0; c < 10; c++) out[b * 10 + c] = lg[c] - lse;
    }
}

// ---------------------------------------------------------------------------
extern "C" void kernel_launch(void* const* d_in, const int* in_sizes, int n_in,
                              void* d_out, int out_size)
{
    const float* x     = (const float*)d_in[0];
    const float* W_in0 = (const float*)d_in[1];
    const float* b_in0 = (const float*)d_in[2];
    const float* W_in1 = (const float*)d_in[3];
    const float* b_in1 = (const float*)d_in[4];
    const float* W_in2 = (const float*)d_in[5];
    const float* b_in2 = (const float*)d_in[6];
    const float* W_e0  = (const float*)d_in[7];
    const float* b_e0  = (const float*)d_in[8];
    const float* W_e1  = (const float*)d_in[9];
    const float* b_e1  = (const float*)d_in[10];
    const float* W_o0  = (const float*)d_in[11];
    const float* b_o0  = (const float*)d_in[12];
    const float* W_o1  = (const float*)d_in[13];
    const float* b_o1  = (const float*)d_in[14];
    const float* W_o2  = (const float*)d_in[15];
    const float* b_o2  = (const float*)d_in[16];

    void *pA, *pB, *pV, *pI;
    cudaGetSymbolAddress(&pA, g_hA);
    cudaGetSymbolAddress(&pB, g_hB);
    cudaGetSymbolAddress(&pV, g_av);
    cudaGetSymbolAddress(&pI, g_idx);
    float* hA = (float*)pA;
    float* hB = (float*)pB;
    float* avp = (float*)pV;
    int*   nb = (int*)pI;

    cudaFuncSetAttribute(knn_kernel,  cudaFuncAttributeMaxDynamicSharedMemorySize, KNN_SMEM);
    cudaFuncSetAttribute(edge_kernel, cudaFuncAttributeMaxDynamicSharedMemorySize, EDGE_SMEM);

    input_kernel<<<BB * NN / 16, 256>>>(x, W_in0, b_in0, W_in1, b_in1, W_in2, b_in2, hA);

    for (int l = 0; l < 2; l++) {
        const float* src = l ? hB : hA;
        float*       dst = l ? hA : hB;
        knn_kernel<<<BB, 512, KNN_SMEM>>>(src, nb);
        av_kernel<<<148, 256>>>(src, W_e0 + (size_t)l * 2 * HH * HH,
                                b_e0 + (size_t)l * HH, avp);
        edge_kernel<<<444, 192, EDGE_SMEM>>>(
            avp, nb,
            W_e1 + (size_t)l * HH * HH, b_e1 + (size_t)l * HH,
            dst);
    }

    pool_kernel<<<BB, 64>>>(hA, W_o0, b_o0, W_o1, b_o1, W_o2, b_o2, (float*)d_out);
}

// round 14
// speedup vs baseline: 1.4532x; 1.4532x over previous
#include <cuda_runtime.h>
#include <cstdint>

#define BB 128
#define NN 512
#define FF 5
#define HH 64
#define KK 16

typedef unsigned long long u64;

// Scratch (device globals: allocation-free)
__device__ __align__(256) float g_hA[BB * NN * HH];        // 16 MB
__device__ __align__(256) float g_hB[BB * NN * HH];        // 16 MB
__device__ __align__(256) float g_av[BB * NN * 2 * HH];    // 32 MB: per node [c | v]
__device__ __align__(256) int   g_idx[BB * NN * KK];       // 4 MB

__device__ __forceinline__ float elu_f(float x) {
    return x > 0.f ? x : (__expf(x) - 1.f);
}

// ---- packed fp32x2 helpers (Blackwell FFMA2; exact fp32) ---------------
__device__ __forceinline__ u64 fma2_(u64 a, u64 b, u64 c) {
    u64 d;
    asm("fma.rn.f32x2 %0, %1, %2, %3;" : "=l"(d) : "l"(a), "l"(b), "l"(c));
    return d;
}
__device__ __forceinline__ u64 pack2_(float x) {
    u64 d;
    asm("mov.b64 %0, {%1, %1};" : "=l"(d) : "f"(x));
    return d;
}
__device__ __forceinline__ float2 unpack2_(u64 v) {
    float2 r;
    asm("mov.b64 {%0, %1}, %2;" : "=f"(r.x), "=f"(r.y) : "l"(v));
    return r;
}
__device__ __forceinline__ uint32_t smem_u32(const void* p) {
    uint32_t a;
    asm("{ .reg .u64 t; cvta.to.shared.u64 t, %1; cvt.u32.u64 %0, t; }" : "=r"(a) : "l"(p));
    return a;
}
__device__ __forceinline__ void cpasync16(uint32_t saddr, const void* g) {
    asm volatile("cp.async.cg.shared.global [%0], [%1], 16;" :: "r"(saddr), "l"(g));
}
#define CP_COMMIT() asm volatile("cp.async.commit_group;" ::: "memory")
#define CP_WAIT1()  asm volatile("cp.async.wait_group 1;" ::: "memory")

// ---------------------------------------------------------------------------
// Input MLP: x[B,N,5] -> h[B,N,64], three elu layers.
// ---------------------------------------------------------------------------
__global__ __launch_bounds__(256) void input_kernel(
    const float* __restrict__ x,
    const float* __restrict__ W0, const float* __restrict__ b0,
    const float* __restrict__ W1, const float* __restrict__ b1,
    const float* __restrict__ W2, const float* __restrict__ b2,
    float* __restrict__ out)
{
    __shared__ float sW0[FF * HH];
    __shared__ float sW1[HH * HH];
    __shared__ float sW2[HH * HH];
    __shared__ float sx[16][FF];
    __shared__ float sh[16][HH];

    int tid = threadIdx.x;
    for (int t = tid; t < FF * HH; t += 256) sW0[t] = W0[t];
    for (int t = tid; t < HH * HH; t += 256) { sW1[t] = W1[t]; sW2[t] = W2[t]; }

    int node0 = blockIdx.x * 16;
    if (tid < 16 * FF) sx[tid / FF][tid % FF] = x[(size_t)(node0 + tid / FF) * FF + tid % FF];
    __syncthreads();

    int nl = tid >> 4, tn = tid & 15;

    float4 acc = *(const float4*)(b0 + tn * 4);
    #pragma unroll
    for (int d = 0; d < FF; d++) {
        float v = sx[nl][d];
        float4 w = *(const float4*)(sW0 + d * HH + tn * 4);
        acc.x = fmaf(v, w.x, acc.x); acc.y = fmaf(v, w.y, acc.y);
        acc.z = fmaf(v, w.z, acc.z); acc.w = fmaf(v, w.w, acc.w);
    }
    acc.x = elu_f(acc.x); acc.y = elu_f(acc.y); acc.z = elu_f(acc.z); acc.w = elu_f(acc.w);
    ((float4*)(sh[nl]))[tn] = acc;
    __syncthreads();

    float4 a2 = *(const float4*)(b1 + tn * 4);
    #pragma unroll 8
    for (int d = 0; d < HH; d++) {
        float v = sh[nl][d];
        float4 w = *(const float4*)(sW1 + d * HH + tn * 4);
        a2.x = fmaf(v, w.x, a2.x); a2.y = fmaf(v, w.y, a2.y);
        a2.z = fmaf(v, w.z, a2.z); a2.w = fmaf(v, w.w, a2.w);
    }
    __syncthreads();
    a2.x = elu_f(a2.x); a2.y = elu_f(a2.y); a2.z = elu_f(a2.z); a2.w = elu_f(a2.w);
    ((float4*)(sh[nl]))[tn] = a2;
    __syncthreads();

    float4 a3 = *(const float4*)(b2 + tn * 4);
    #pragma unroll 8
    for (int d = 0; d < HH; d++) {
        float v = sh[nl][d];
        float4 w = *(const float4*)(sW2 + d * HH + tn * 4);
        a3.x = fmaf(v, w.x, a3.x); a3.y = fmaf(v, w.y, a3.y);
        a3.z = fmaf(v, w.z, a3.z); a3.w = fmaf(v, w.w, a3.w);
    }
    a3.x = elu_f(a3.x); a3.y = elu_f(a3.y); a3.z = elu_f(a3.z); a3.w = elu_f(a3.w);
    *(float4*)(out + (size_t)(node0 + nl) * HH + tn * 4) = a3;
}

// ---------------------------------------------------------------------------
// kNN: candidate-queue top-k, now with 4 independent FFMA2 chains per j-pair
// (halved RAW critical path) and the top-16 index array packed 2-per-register
// (frees 8 regs to stay under the 128-reg cap at 512 threads).
// ---------------------------------------------------------------------------
#define STK_CAP 8
#define STK_STRIDE 9
#define KNN_SMEM ((NN * HH + NN) * 4 + NN * STK_STRIDE * 8)

// bd[16] floats; indices packed: bip[8], slot t -> half (t&1) of bip[t>>1]
#define TOPK_INSERT(DJ, J)                                                   \
    if ((DJ) < worst) {                                                      \
        _Pragma("unroll")                                                    \
        for (int t = 0; t < KK; t++) if (t == wslot) {                       \
            bd[t] = (DJ);                                                    \
            if (t & 1) bip[t >> 1] = (bip[t >> 1] & 0x0000FFFFu)             \
                                     | ((unsigned)(J) << 16);                \
            else       bip[t >> 1] = (bip[t >> 1] & 0xFFFF0000u)             \
                                     | (unsigned)(J);                        \
        }                                                                    \
        float w_ = bd[0]; int ws_ = 0;                                       \
        _Pragma("unroll")                                                    \
        for (int t = 1; t < KK; t++) if (bd[t] > w_) { w_ = bd[t]; ws_ = t; } \
        worst = w_; wslot = ws_;                                             \
    }

__global__ __launch_bounds__(512, 1) void knn_kernel(
    const float* __restrict__ h, int* __restrict__ nbr)
{
    extern __shared__ float sm[];
    float* sq = sm + NN * HH;
    u64* stkbase = (u64*)(sm + NN * HH + NN);
    int b = blockIdx.x, i = threadIdx.x;
    u64* stk = stkbase + i * STK_STRIDE;

    const float4* src4 = (const float4*)(h + (size_t)b * NN * HH);
    float4* dst4 = (float4*)sm;
    for (int t = i; t < NN * HH / 4; t += NN) dst4[t] = src4[t];
    __syncthreads();

    u64 rp[HH / 2];
    const ulonglong2* myrow = (const ulonglong2*)(sm + i * HH);
    #pragma unroll
    for (int q = 0; q < HH / 4; q++) {
        ulonglong2 v = myrow[q];
        rp[2 * q] = v.x; rp[2 * q + 1] = v.y;
    }
    u64 s2 = 0ull;
    #pragma unroll
    for (int q = 0; q < HH / 2; q++) s2 = fma2_(rp[q], rp[q], s2);
    float2 sf = unpack2_(s2);
    float s = sf.x + sf.y;
    sq[i] = s;
    __syncthreads();

    float bd[KK]; unsigned bip[KK / 2];
    #pragma unroll
    for (int t = 0; t < KK; t++) bd[t] = 1e30f;
    #pragma unroll
    for (int t = 0; t < KK / 2; t++) bip[t] = 0u;
    float worst = 1e30f; int wslot = 0;

    // distance for rows j, j+1 with 4 independent 8-deep fma2 chains
    #define KNN_DIST2(DJ0, DJ1, JROW)                                         \
    {                                                                         \
        const ulonglong2* r0_ = (const ulonglong2*)(sm + (JROW) * HH);        \
        const ulonglong2* r1_ = (const ulonglong2*)(sm + (JROW) * HH + HH);   \
        u64 a0a = 0ull, a0b = 0ull, a1a = 0ull, a1b = 0ull;                   \
        _Pragma("unroll")                                                     \
        for (int q = 0; q < HH / 4; q += 2) {                                 \
            ulonglong2 va0 = r0_[q];                                          \
            a0a = fma2_(rp[2 * q], va0.x, a0a);                               \
            a0a = fma2_(rp[2 * q + 1], va0.y, a0a);                           \
            ulonglong2 vb0 = r0_[q + 1];                                      \
            a0b = fma2_(rp[2 * q + 2], vb0.x, a0b);                           \
            a0b = fma2_(rp[2 * q + 3], vb0.y, a0b);                           \
            ulonglong2 va1 = r1_[q];                                          \
            a1a = fma2_(rp[2 * q], va1.x, a1a);                               \
            a1a = fma2_(rp[2 * q + 1], va1.y, a1a);                           \
            ulonglong2 vb1 = r1_[q + 1];                                      \
            a1b = fma2_(rp[2 * q + 2], vb1.x, a1b);                           \
            a1b = fma2_(rp[2 * q + 3], vb1.y, a1b);                           \
        }                                                                     \
        float2 f0a = unpack2_(a0a), f0b = unpack2_(a0b);                      \
        float2 f1a = unpack2_(a1a), f1b = unpack2_(a1b);                      \
        (DJ0) = s + sq[(JROW)]     - 2.f * ((f0a.x + f0a.y) + (f0b.x + f0b.y)); \
        (DJ1) = s + sq[(JROW) + 1] - 2.f * ((f1a.x + f1a.y) + (f1b.x + f1b.y)); \
    }

    // warm-up: first 32 j's inserted exactly (ascending) to tighten 'worst'
    for (int j = 0; j < 32; j += 2) {
        float dj0, dj1;
        KNN_DIST2(dj0, dj1, j)
        if (j == i)     dj0 = 1e30f;
        if (j + 1 == i) dj1 = 1e30f;
        TOPK_INSERT(dj0, j)
        TOPK_INSERT(dj1, j + 1)
    }

    int cnt = 0;
    for (int j = 32; j < NN; j += 2) {
        float dj0, dj1;
        KNN_DIST2(dj0, dj1, j)
        if (j == i)     dj0 = 1e30f;
        if (j + 1 == i) dj1 = 1e30f;

        if (dj0 < worst) { stk[cnt] = ((u64)__float_as_uint(dj0) << 32) | (unsigned)j; cnt++; }
        if (dj1 < worst) { stk[cnt] = ((u64)__float_as_uint(dj1) << 32) | (unsigned)(j + 1); cnt++; }
        if (__any_sync(0xffffffffu, cnt >= STK_CAP - 1)) {
            #pragma unroll
            for (int t = 0; t < STK_CAP; t++) {
                if (t < cnt) {
                    u64 e = stk[t];
                    float dd = __uint_as_float((unsigned)(e >> 32));
                    int jj = (int)(e & 0xffffffffull);
                    TOPK_INSERT(dd, jj)
                }
            }
            cnt = 0;
        }
    }
    #pragma unroll
    for (int t = 0; t < STK_CAP; t++) {
        if (t < cnt) {
            u64 e = stk[t];
            float dd = __uint_as_float((unsigned)(e >> 32));
            int jj = (int)(e & 0xffffffffull);
            TOPK_INSERT(dd, jj)
        }
    }

    #pragma unroll
    for (int t = 0; t < KK; t++) {
        unsigned idx = (t & 1) ? (bip[t >> 1] >> 16) : (bip[t >> 1] & 0xFFFFu);
        nbr[((size_t)b * NN + i) * KK + t] = (int)idx;
    }
}

// ---------------------------------------------------------------------------
// Per-node precompute: c = h@W0top + b0 - h@W0bot, v = h@W0bot.
// (E row = elu(c_i + v_j).)  av[n] = [c(64) | v(64)].
// ---------------------------------------------------------------------------
#define AV_GROUPS (BB * NN / 16)   // 4096

__global__ __launch_bounds__(256, 1) void av_kernel(
    const float* __restrict__ h,
    const float* __restrict__ W0, const float* __restrict__ b0,
    float* __restrict__ av)
{
    __shared__ float sW[2 * HH * HH];    // 32 KB (top | bottom)
    __shared__ float sh[16][HH];
    __shared__ float sb[HH];

    int tid = threadIdx.x;
    for (int t = tid; t < 2 * HH * HH; t += 256) sW[t] = W0[t];
    if (tid < HH) sb[tid] = b0[tid];
    __syncthreads();

    int nl = tid >> 4, tn = tid & 15;

    for (int grp = blockIdx.x; grp < AV_GROUPS; grp += gridDim.x) {
        int node0 = grp * 16;
        {
            int row = tid >> 4, q = tid & 15;
            ((float4*)sh[row])[q] = *(const float4*)(h + (size_t)(node0 + row) * HH + q * 4);
        }
        __syncthreads();

        float4 aA = *(const float4*)(sb + tn * 4);
        float4 aV = make_float4(0.f, 0.f, 0.f, 0.f);
        #pragma unroll 8
        for (int d = 0; d < HH; d++) {
            float v = sh[nl][d];
            float4 wt = *(const float4*)(sW + d * HH + tn * 4);
            float4 wb = *(const float4*)(sW + (HH + d) * HH + tn * 4);
            aA.x = fmaf(v, wt.x, aA.x); aA.y = fmaf(v, wt.y, aA.y);
            aA.z = fmaf(v, wt.z, aA.z); aA.w = fmaf(v, wt.w, aA.w);
            aV.x = fmaf(v, wb.x, aV.x); aV.y = fmaf(v, wb.y, aV.y);
            aV.z = fmaf(v, wb.z, aV.z); aV.w = fmaf(v, wb.w, aV.w);
        }
        float4 cC = make_float4(aA.x - aV.x, aA.y - aV.y, aA.z - aV.z, aA.w - aV.w);
        *(float4*)(av + (size_t)(node0 + nl) * 128 + tn * 4) = cC;
        *(float4*)(av + (size_t)(node0 + nl) * 128 + 64 + tn * 4) = aV;
        __syncthreads();
    }
}

// ---------------------------------------------------------------------------
// EdgeConv — ROUND-12 version (proven fastest): warp-autonomous, cp.async
// double-buffered gather, 8-row x 4-col lane tile, 256 threads, 2 CTAs/SM.
// ---------------------------------------------------------------------------
#define ED_B1f  4096
#define ED_BUFf 4160
#define ED_WBUF 2304                 // floats per warp (2 bufs x 1152)
#define EDGE_FLOATS (ED_BUFf + 8 * ED_WBUF)
#define EDGE_SMEM (EDGE_FLOATS * 4)
#define ED_TOT (BB * NN)

__global__ __launch_bounds__(256, 2) void edge_kernel(
    const float* __restrict__ av, const int* __restrict__ nbr,
    const float* __restrict__ W1, const float* __restrict__ b1,
    float* __restrict__ out)
{
    extern __shared__ float sm[];
    float* sW1 = sm;
    float* sB1 = sm + ED_B1f;

    int tid = threadIdx.x, wid = tid >> 5, lid = tid & 31;
    float* wbase = sm + ED_BUFf + wid * ED_WBUF;
    uint32_t wbase_u = smem_u32(wbase);

    {   // weights + bias once
        const float4* w14 = (const float4*)W1; float4* s14 = (float4*)sW1;
        for (int t = tid; t < 1024; t += 256) s14[t] = w14[t];
        if (tid < 64) sB1[tid] = b1[tid];
    }
    __syncthreads();

    int mrow = lid >> 1, half = lid & 1;          // gather/build: row, col-half
    int tmp = lid >> 4, tn = lid & 15;            // GEMM: row-group, col-quad
    int m0 = tmp * 8;
    int c0 = half * 32;

    int nwarps = gridDim.x * 8;
    int ni0 = blockIdx.x * 8 + wid;

    // ---- prologue: cp.async item ni0 into buf 0
    {
        int j0 = nbr[(size_t)ni0 * KK + mrow];
        uint32_t dstV = wbase_u + (uint32_t)((mrow * 68 + c0) * 4);
        const float* srcV = av + ((size_t)(ni0 & ~(NN - 1)) + j0) * 128 + 64 + c0;
        #pragma unroll
        for (int q = 0; q < 8; q++) cpasync16(dstV + q * 16, srcV + q * 4);
        if (lid < 16)
            cpasync16(wbase_u + (uint32_t)((1088 + lid * 4) * 4),
                      av + (size_t)ni0 * 128 + lid * 4);
    }
    CP_COMMIT();
    int jn1 = (ni0 + nwarps < ED_TOT) ? nbr[(size_t)(ni0 + nwarps) * KK + mrow] : 0;

    int bsel = 0;
    for (int ni = ni0; ni < ED_TOT; ni += nwarps) {
        int ni1 = ni + nwarps;
        int ni2 = ni + 2 * nwarps;
        int jn2 = (ni2 < ED_TOT) ? nbr[(size_t)ni2 * KK + mrow] : 0;

        // ---- cp.async item i+1 into the other buffer
        if (ni1 < ED_TOT) {
            uint32_t bb = (uint32_t)((bsel ^ 1) * 1152);
            uint32_t dstV = wbase_u + (bb + (uint32_t)(mrow * 68 + c0)) * 4;
            const float* srcV = av + ((size_t)(ni1 & ~(NN - 1)) + jn1) * 128 + 64 + c0;
            #pragma unroll
            for (int q = 0; q < 8; q++) cpasync16(dstV + q * 16, srcV + q * 4);
            if (lid < 16)
                cpasync16(wbase_u + (bb + 1088u + (uint32_t)(lid * 4)) * 4,
                          av + (size_t)ni1 * 128 + lid * 4);
        }
        CP_COMMIT();

        // ---- current buffer is complete (committed one iteration ago)
        CP_WAIT1();
        __syncwarp();

        float* rawV = wbase + bsel * 1152;
        float* rawC = rawV + 1088;

        // ---- E-build: in-place elu(c_i + v_j) on own slots
        {
            float4* e4 = (float4*)(rawV + mrow * 68 + c0);
            const float4* cc = (const float4*)(rawC + c0);
            #pragma unroll
            for (int q = 0; q < 8; q++) {
                float4 c = cc[q], v = e4[q];
                float4 e;
                e.x = elu_f(c.x + v.x);
                e.y = elu_f(c.y + v.y);
                e.z = elu_f(c.z + v.z);
                e.w = elu_f(c.w + v.w);
                e4[q] = e;
            }
        }
        __syncwarp();

        // ---- GEMM2: E(16x64) @ W1(64x64), lane: rows m0..m0+7, cols tn*4..+4
        u64 acc[8][2];
        #pragma unroll
        for (int r = 0; r < 8; r++) { acc[r][0] = 0ull; acc[r][1] = 0ull; }
        #pragma unroll 2
        for (int d0 = 0; d0 < HH; d0 += 4) {
            float4 ev[8];
            #pragma unroll
            for (int r = 0; r < 8; r++)
                ev[r] = *(const float4*)(rawV + (m0 + r) * 68 + d0);
            #pragma unroll
            for (int dd = 0; dd < 4; dd++) {
                ulonglong2 w2 = *(const ulonglong2*)(sW1 + (d0 + dd) * HH + tn * 4);
                #pragma unroll
                for (int r = 0; r < 8; r++) {
                    float a = (dd == 0) ? ev[r].x : (dd == 1) ? ev[r].y
                            : (dd == 2) ? ev[r].z : ev[r].w;
                    u64 a2 = pack2_(a);
                    acc[r][0] = fma2_(a2, w2.x, acc[r][0]);
                    acc[r][1] = fma2_(a2, w2.y, acc[r][1]);
                }
            }
        }

        // ---- epilogue: bias + elu + 8-row sum, combine halves via shfl
        float4 bb4 = *(const float4*)(sB1 + tn * 4);
        float s0 = 0.f, s1 = 0.f, s2 = 0.f, s3 = 0.f;
        #pragma unroll
        for (int r = 0; r < 8; r++) {
            float2 p0 = unpack2_(acc[r][0]);
            float2 p1 = unpack2_(acc[r][1]);
            s0 += elu_f(p0.x + bb4.x);
            s1 += elu_f(p0.y + bb4.y);
            s2 += elu_f(p1.x + bb4.z);
            s3 += elu_f(p1.y + bb4.w);
        }
        // shfl doubles as the warp barrier: all GEMM reads of rawV complete
        // before the next iteration's in-place build overwrites it.
        s0 += __shfl_down_sync(0xffffffffu, s0, 16);
        s1 += __shfl_down_sync(0xffffffffu, s1, 16);
        s2 += __shfl_down_sync(0xffffffffu, s2, 16);
        s3 += __shfl_down_sync(0xffffffffu, s3, 16);
        if (lid < 16)
            *(float4*)(out + (size_t)ni * HH + tn * 4) = make_float4(s0, s1, s2, s3);

        jn1 = jn2;
        bsel ^= 1;
    }
}

// ---------------------------------------------------------------------------
// Global max-pool + output MLP + log_softmax. One CTA (64 threads) per graph.
// ---------------------------------------------------------------------------
__global__ __launch_bounds__(64) void pool_kernel(
    const float* __restrict__ h,
    const float* __restrict__ W0, const float* __restrict__ b0,
    const float* __restrict__ W1, const float* __restrict__ b1,
    const float* __restrict__ W2, const float* __restrict__ b2,
    float* __restrict__ out)
{
    __shared__ float sW0[HH * HH], sW1[HH * HH], sW2[HH * 10];
    __shared__ float g0[HH], g1[HH], lg[10];

    int b = blockIdx.x, f = threadIdx.x;
    for (int t = f; t < HH * HH; t += 64) { sW0[t] = W0[t]; sW1[t] = W1[t]; }
    for (int t = f; t < HH * 10; t += 64) sW2[t] = W2[t];

    const float* hb = h + (size_t)b * NN * HH;
    float m0 = -1e30f, m1 = -1e30f, m2 = -1e30f, m3 = -1e30f;
    #pragma unroll 4
    for (int n = 0; n < NN; n += 4) {
        m0 = fmaxf(m0, hb[(n + 0) * HH + f]);
        m1 = fmaxf(m1, hb[(n + 1) * HH + f]);
        m2 = fmaxf(m2, hb[(n + 2) * HH + f]);
        m3 = fmaxf(m3, hb[(n + 3) * HH + f]);
    }
    g0[f] = fmaxf(fmaxf(m0, m1), fmaxf(m2, m3));
    __syncthreads();

    float acc = b0[f];
    #pragma unroll 8
    for (int d = 0; d < HH; d++) acc = fmaf(g0[d], sW0[d * HH + f], acc);
    g1[f] = elu_f(acc);
    __syncthreads();

    acc = b1[f];
    #pragma unroll 8
    for (int d = 0; d < HH; d++) acc = fmaf(g1[d], sW1[d * HH + f], acc);
    __syncthreads();
    g0[f] = elu_f(acc);
    __syncthreads();

    if (f < 10) {
        float a = b2[f];
        #pragma unroll 8
        for (int d = 0; d < HH; d++) a = fmaf(g0[d], sW2[d * 10 + f], a);
        lg[f] = a;
    }
    __syncthreads();

    if (f == 0) {
        float mx = lg[0];
        #pragma unroll
        for (int c = 1; c < 10; c++) mx = fmaxf(mx, lg[c]);
        float se = 0.f;
        #pragma unroll
        for (int c = 0; c < 10; c++) se += expf(lg[c] - mx);
        float lse = mx + logf(se);
        #pragma unroll
        for (int c = 0; c < 10; c++) out[b * 10 + c] = lg[c] - lse;
    }
}

// ---------------------------------------------------------------------------
extern "C" void kernel_launch(void* const* d_in, const int* in_sizes, int n_in,
                              void* d_out, int out_size)
{
    const float* x     = (const float*)d_in[0];
    const float* W_in0 = (const float*)d_in[1];
    const float* b_in0 = (const float*)d_in[2];
    const float* W_in1 = (const float*)d_in[3];
    const float* b_in1 = (const float*)d_in[4];
    const float* W_in2 = (const float*)d_in[5];
    const float* b_in2 = (const float*)d_in[6];
    const float* W_e0  = (const float*)d_in[7];
    const float* b_e0  = (const float*)d_in[8];
    const float* W_e1  = (const float*)d_in[9];
    const float* b_e1  = (const float*)d_in[10];
    const float* W_o0  = (const float*)d_in[11];
    const float* b_o0  = (const float*)d_in[12];
    const float* W_o1  = (const float*)d_in[13];
    const float* b_o1  = (const float*)d_in[14];
    const float* W_o2  = (const float*)d_in[15];
    const float* b_o2  = (const float*)d_in[16];

    void *pA, *pB, *pV, *pI;
    cudaGetSymbolAddress(&pA, g_hA);
    cudaGetSymbolAddress(&pB, g_hB);
    cudaGetSymbolAddress(&pV, g_av);
    cudaGetSymbolAddress(&pI, g_idx);
    float* hA = (float*)pA;
    float* hB = (float*)pB;
    float* avp = (float*)pV;
    int*   nb = (int*)pI;

    cudaFuncSetAttribute(knn_kernel,  cudaFuncAttributeMaxDynamicSharedMemorySize, KNN_SMEM);
    cudaFuncSetAttribute(edge_kernel, cudaFuncAttributeMaxDynamicSharedMemorySize, EDGE_SMEM);

    input_kernel<<<BB * NN / 16, 256>>>(x, W_in0, b_in0, W_in1, b_in1, W_in2, b_in2, hA);

    for (int l = 0; l < 2; l++) {
        const float* src = l ? hB : hA;
        float*       dst = l ? hA : hB;
        knn_kernel<<<BB, 512, KNN_SMEM>>>(src, nb);
        av_kernel<<<148, 256>>>(src, W_e0 + (size_t)l * 2 * HH * HH,
                                b_e0 + (size_t)l * HH, avp);
        edge_kernel<<<296, 256, EDGE_SMEM>>>(
            avp, nb,
            W_e1 + (size_t)l * HH * HH, b_e1 + (size_t)l * HH,
            dst);
    }

    pool_kernel<<<BB, 64>>>(hA, W_o0, b_o0, W_o1, b_o1, W_o2, b_o2, (float*)d_out);
}